// round 16
// baseline (speedup 1.0000x reference)
#include <cuda_runtime.h>
#include <cuda_fp16.h>
#include <cstdint>

#define D_MODEL 1024
#define NHEAD 16
#define D_HEAD 64
#define D_FF 4096
#define BATCH 2
#define SEQ 2048
#define NTOK (BATCH*SEQ)   /* 4096 tokens */
#define LN_EPS 1e-5f

/* ------------------------------------------------------------------ */
/* Scratch (static __device__ arrays; no runtime allocation)           */
/* ------------------------------------------------------------------ */
__device__ float  g_proj[(size_t)NTOK * D_MODEL];
__device__ float  g_h   [(size_t)NTOK * D_MODEL];
__device__ float  g_f2  [(size_t)NTOK * D_MODEL];

__device__ __half g_x16  [(size_t)NTOK * D_MODEL];
__device__ __half g_wq16 [(size_t)D_MODEL * D_MODEL];
__device__ __half g_wk16 [(size_t)D_MODEL * D_MODEL];
__device__ __half g_wv16 [(size_t)D_MODEL * D_MODEL];
__device__ __half g_wo16 [(size_t)D_MODEL * D_MODEL];
__device__ __half g_w116 [(size_t)D_FF * D_MODEL];
__device__ __half g_w216 [(size_t)D_MODEL * D_FF];
__device__ __half g_q16  [(size_t)NTOK * D_MODEL];
__device__ __half g_k16  [(size_t)NTOK * D_MODEL];
__device__ __half g_v16  [(size_t)NTOK * D_MODEL];
__device__ __half g_att16[(size_t)NTOK * D_MODEL];
__device__ __half g_h16  [(size_t)NTOK * D_MODEL];
__device__ __half g_ffn16[(size_t)NTOK * D_FF];

/* fp16 MMA, fp32 accumulate */
#define MMA_F16(acc, a, b0, b1)                                         \
    asm volatile(                                                       \
        "mma.sync.aligned.m16n8k16.row.col.f32.f16.f16.f32 "            \
        "{%0,%1,%2,%3}, {%4,%5,%6,%7}, {%8,%9}, {%0,%1,%2,%3};\n"       \
        : "+f"(acc[0]), "+f"(acc[1]), "+f"(acc[2]), "+f"(acc[3])        \
        : "r"(a[0]), "r"(a[1]), "r"(a[2]), "r"(a[3]), "r"(b0), "r"(b1))

#define LDSM_X4_TRANS(d0, d1, d2, d3, addr)                             \
    asm volatile(                                                       \
        "ldmatrix.sync.aligned.m8n8.x4.trans.shared.b16 "               \
        "{%0,%1,%2,%3}, [%4];"                                          \
        : "=r"(d0), "=r"(d1), "=r"(d2), "=r"(d3) : "r"(addr))

__device__ __forceinline__ void cpa16(void* s, const void* g) {
    uint32_t sa = (uint32_t)__cvta_generic_to_shared(s);
    asm volatile("cp.async.cg.shared.global [%0], [%1], 16;" :: "r"(sa), "l"(g));
}
#define CP_COMMIT() asm volatile("cp.async.commit_group;")
#define CP_WAIT0()  asm volatile("cp.async.wait_group 0;")
#define CP_WAIT1()  asm volatile("cp.async.wait_group 1;")

__device__ __forceinline__ uint32_t packh2(float a, float b) {
    __half2 h = __floats2half2_rn(a, b);
    return *(uint32_t*)&h;
}

/* ------------------------------------------------------------------ */
/* fused fp32 -> fp16 convert: all 7 tensors in ONE launch.            */
/* Segment layout (units of 1M = 1<<20 elems):                         */
/*   [0,4): x   [4,5): Wq  [5,6): Wk  [6,7): Wv  [7,8): Wo             */
/*   [8,12): W1 [12,16): W2    -- 16M elems total                      */
/* 8 elems/thread, 2048 elems/CTA; every boundary is 1M-aligned so no  */
/* CTA straddles segments.                                             */
/* ------------------------------------------------------------------ */
struct ConvAll {
    const float* s[7];
    __half*      d[7];
};

__global__ __launch_bounds__(256)
void f2h_all_kernel(ConvAll p)
{
    const size_t M1 = 1u << 20;
    size_t i = ((size_t)blockIdx.x * 256 + threadIdx.x) * 8;

    int seg; size_t off;
    if      (i <  4*M1) { seg = 0; off = 0;     }
    else if (i <  5*M1) { seg = 1; off = 4*M1;  }
    else if (i <  6*M1) { seg = 2; off = 5*M1;  }
    else if (i <  7*M1) { seg = 3; off = 6*M1;  }
    else if (i <  8*M1) { seg = 4; off = 7*M1;  }
    else if (i < 12*M1) { seg = 5; off = 8*M1;  }
    else                { seg = 6; off = 12*M1; }

    const float* s = p.s[seg];
    __half*      d = p.d[seg];
    const size_t j = i - off;

    float4 a = *(const float4*)&s[j];
    float4 b = *(const float4*)&s[j + 4];
    __half2 h0 = __floats2half2_rn(a.x, a.y);
    __half2 h1 = __floats2half2_rn(a.z, a.w);
    __half2 h2 = __floats2half2_rn(b.x, b.y);
    __half2 h3 = __floats2half2_rn(b.z, b.w);
    uint4 o;
    o.x = *(uint32_t*)&h0; o.y = *(uint32_t*)&h1;
    o.z = *(uint32_t*)&h2; o.w = *(uint32_t*)&h3;
    *(uint4*)&d[j] = o;
}

/* ------------------------------------------------------------------ */
/* fp16 GEMM:  C[M,N] = A[M,K] @ B[N,K]^T + bias (opt ReLU, opt fp16)  */
/* (validated R14/R15; unchanged)                                      */
/* ------------------------------------------------------------------ */
#define GST 40
#define GTILE_H (128 * GST)
#define GSTAGES 3
#define GEMM_SMEM_B (GSTAGES * 2 * GTILE_H * (int)sizeof(__half))

template<bool RELU, bool HOUT>
__device__ __forceinline__
void gemm_h_body(const __half* __restrict__ A,
                 const __half* __restrict__ B,
                 const float* __restrict__ bias,
                 float* __restrict__ C,
                 __half* __restrict__ C16,
                 int N, int K, __half* smem)
{
    const int bm0 = blockIdx.y * 128;
    const int bn0 = blockIdx.x * 128;
    const int t    = threadIdx.x;
    const int warp = t >> 5, lane = t & 31;
    const int wm = (warp >> 2) * 64;
    const int wn = (warp & 3) * 32;
    const int r  = lane >> 2;
    const int c  = lane & 3;

    __half* As = smem;
    __half* Bs = smem + GSTAGES * GTILE_H;

    float acc[4][4][4];
#pragma unroll
    for (int mt = 0; mt < 4; mt++)
#pragma unroll
        for (int nt = 0; nt < 4; nt++)
#pragma unroll
            for (int i = 0; i < 4; i++) acc[mt][nt][i] = 0.f;

    int g_row[2], g_sg[2];
#pragma unroll
    for (int i = 0; i < 2; i++) {
        int slot = t + i * 256;
        g_row[i] = slot >> 2;
        g_sg[i]  = slot & 3;
    }

    const int niter = K >> 5;

#pragma unroll
    for (int s = 0; s < GSTAGES - 1; ++s) {
        const int k0 = s << 5;
#pragma unroll
        for (int i = 0; i < 2; i++) {
            cpa16(&As[s * GTILE_H + g_row[i] * GST + g_sg[i] * 8],
                  A + (size_t)(bm0 + g_row[i]) * K + k0 + g_sg[i] * 8);
            cpa16(&Bs[s * GTILE_H + g_row[i] * GST + g_sg[i] * 8],
                  B + (size_t)(bn0 + g_row[i]) * K + k0 + g_sg[i] * 8);
        }
        CP_COMMIT();
    }

    int buf = 0;
    for (int it = 0; it < niter; ++it) {
        CP_WAIT1();
        __syncthreads();

        const __half* Ab = As + buf * GTILE_H;
        const __half* Bb = Bs + buf * GTILE_H;
#pragma unroll
        for (int ks = 0; ks < 2; ++ks) {
            const int kk = ks * 16;
            uint32_t af[4][4], bf[4][2];
#pragma unroll
            for (int mt = 0; mt < 4; mt++) {
                const int m0 = wm + mt * 16;
                af[mt][0] = *(const uint32_t*)&Ab[(m0 + r    ) * GST + kk + 2*c    ];
                af[mt][1] = *(const uint32_t*)&Ab[(m0 + r + 8) * GST + kk + 2*c    ];
                af[mt][2] = *(const uint32_t*)&Ab[(m0 + r    ) * GST + kk + 2*c + 8];
                af[mt][3] = *(const uint32_t*)&Ab[(m0 + r + 8) * GST + kk + 2*c + 8];
            }
#pragma unroll
            for (int nt = 0; nt < 4; nt++) {
                const int n0 = wn + nt * 8;
                bf[nt][0] = *(const uint32_t*)&Bb[(n0 + r) * GST + kk + 2*c    ];
                bf[nt][1] = *(const uint32_t*)&Bb[(n0 + r) * GST + kk + 2*c + 8];
            }
#pragma unroll
            for (int mt = 0; mt < 4; mt++)
#pragma unroll
                for (int nt = 0; nt < 4; nt++)
                    MMA_F16(acc[mt][nt], af[mt], bf[nt][0], bf[nt][1]);
        }

        const int nt_tile = it + GSTAGES - 1;
        if (nt_tile < niter) {
            const int ns = nt_tile % GSTAGES;
            const int k0 = nt_tile << 5;
#pragma unroll
            for (int i = 0; i < 2; i++) {
                cpa16(&As[ns * GTILE_H + g_row[i] * GST + g_sg[i] * 8],
                      A + (size_t)(bm0 + g_row[i]) * K + k0 + g_sg[i] * 8);
                cpa16(&Bs[ns * GTILE_H + g_row[i] * GST + g_sg[i] * 8],
                      B + (size_t)(bn0 + g_row[i]) * K + k0 + g_sg[i] * 8);
            }
            CP_COMMIT();
        }
        buf = (buf + 1 == GSTAGES) ? 0 : buf + 1;
    }

#pragma unroll
    for (int mt = 0; mt < 4; mt++) {
        const int mrow = bm0 + wm + mt * 16 + r;
#pragma unroll
        for (int nt = 0; nt < 4; nt++) {
            const int col = bn0 + wn + nt * 8 + 2 * c;
            const float b0 = bias[col], b1 = bias[col + 1];
            float o0 = acc[mt][nt][0] + b0;
            float o1 = acc[mt][nt][1] + b1;
            float o2 = acc[mt][nt][2] + b0;
            float o3 = acc[mt][nt][3] + b1;
            if (RELU) {
                o0 = fmaxf(o0, 0.f); o1 = fmaxf(o1, 0.f);
                o2 = fmaxf(o2, 0.f); o3 = fmaxf(o3, 0.f);
            }
            if (HOUT) {
                *(__half2*)&C16[(size_t)mrow * N + col]       = __floats2half2_rn(o0, o1);
                *(__half2*)&C16[(size_t)(mrow + 8) * N + col] = __floats2half2_rn(o2, o3);
            } else {
                *(float2*)&C[(size_t)mrow * N + col]       = make_float2(o0, o1);
                *(float2*)&C[(size_t)(mrow + 8) * N + col] = make_float2(o2, o3);
            }
        }
    }
}

template<bool RELU, bool HOUT>
__global__ __launch_bounds__(256, 2)
void gemm_h(const __half* __restrict__ A, const __half* __restrict__ B,
            const float* __restrict__ bias, float* __restrict__ C,
            __half* __restrict__ C16, int N, int K)
{
    extern __shared__ __half hsm[];
    gemm_h_body<RELU, HOUT>(A, B, bias, C, C16, N, K, hsm);
}

struct TriParams {
    const __half* W[3];
    const float*  b[3];
    __half*       C[3];
};

__global__ __launch_bounds__(256, 2)
void gemm_h_qkv(const __half* __restrict__ A, TriParams p, int N, int K)
{
    extern __shared__ __half hsm[];
    const int z = blockIdx.z;
    gemm_h_body<false, true>(A, p.W[z], p.b[z], (float*)0, p.C[z], N, K, hsm);
}

/* ------------------------------------------------------------------ */
/* fp16 tensor-core flash attention (validated R15; unchanged)         */
/* ------------------------------------------------------------------ */
#define AT_STH 72
#define AT_Q_H   (128 * AT_STH)
#define AT_KV_H  (64 * AT_STH)
#define AT_SMEM_B ((AT_Q_H + 4 * AT_KV_H) * (int)sizeof(__half))

__global__ __launch_bounds__(256)
void attn_h_kernel(const __half* __restrict__ Q,
                   const __half* __restrict__ K,
                   const __half* __restrict__ V,
                   __half* __restrict__ O16)
{
    extern __shared__ __half asm_h[];
    __half* Qs = asm_h;
    __half* Ks = asm_h + AT_Q_H;
    __half* Vs = asm_h + AT_Q_H + 2 * AT_KV_H;

    const int b  = blockIdx.z, h = blockIdx.y;
    const int q0 = blockIdx.x * 128;
    const int t = threadIdx.x, w = t >> 5, lane = t & 31;
    const int r = lane >> 2, c = lane & 3;
    const size_t base = ((size_t)b * SEQ) * D_MODEL + (size_t)h * D_HEAD;

#pragma unroll
    for (int i = 0; i < 2; i++) {
        int slot = t + i * 256;
        int row = slot >> 3, sg = slot & 7;
        cpa16(&Ks[row * AT_STH + sg * 8], K + base + (size_t)row * D_MODEL + sg * 8);
        cpa16(&Vs[row * AT_STH + sg * 8], V + base + (size_t)row * D_MODEL + sg * 8);
    }
    CP_COMMIT();

#pragma unroll
    for (int i = 0; i < 4; i++) {
        int slot = t + i * 256;
        int row = slot >> 3, sg = slot & 7;
        cpa16(&Qs[row * AT_STH + sg * 8],
              Q + base + (size_t)(q0 + row) * D_MODEL + sg * 8);
    }
    CP_COMMIT();
    CP_WAIT0();
    __syncthreads();

    uint32_t qf[4][4];
#pragma unroll
    for (int kt = 0; kt < 4; kt++) {
        const int kk = kt * 16;
        qf[kt][0] = *(const uint32_t*)&Qs[(w * 16 + r    ) * AT_STH + kk + 2*c    ];
        qf[kt][1] = *(const uint32_t*)&Qs[(w * 16 + r + 8) * AT_STH + kk + 2*c    ];
        qf[kt][2] = *(const uint32_t*)&Qs[(w * 16 + r    ) * AT_STH + kk + 2*c + 8];
        qf[kt][3] = *(const uint32_t*)&Qs[(w * 16 + r + 8) * AT_STH + kk + 2*c + 8];
    }

    float oacc[8][4];
#pragma unroll
    for (int nt = 0; nt < 8; nt++)
#pragma unroll
        for (int i = 0; i < 4; i++) oacc[nt][i] = 0.f;
    float m0 = -1e30f, m1 = -1e30f, l0 = 0.f, l1 = 0.f;
    const float scale = 0.125f;

    const int lm_row = lane & 15;
    const int lm_col = (lane >> 4) * 8;

    const int ntiles = SEQ / 64;
    for (int it = 0; it < ntiles; ++it) {
        const int buf = it & 1;
        const bool has_next = (it + 1 < ntiles);
        __half* Kb = Ks + buf * AT_KV_H;
        __half* Vb = Vs + buf * AT_KV_H;

        if (has_next) {
            const int k0n = (it + 1) * 64;
            const int nb = buf ^ 1;
#pragma unroll
            for (int i = 0; i < 2; i++) {
                int slot = t + i * 256;
                int row = slot >> 3, sg = slot & 7;
                cpa16(&Ks[nb * AT_KV_H + row * AT_STH + sg * 8],
                      K + base + (size_t)(k0n + row) * D_MODEL + sg * 8);
                cpa16(&Vs[nb * AT_KV_H + row * AT_STH + sg * 8],
                      V + base + (size_t)(k0n + row) * D_MODEL + sg * 8);
            }
            CP_COMMIT();
            CP_WAIT1();
        } else {
            CP_WAIT0();
        }
        __syncthreads();

        float sacc[8][4];
#pragma unroll
        for (int nt = 0; nt < 8; nt++)
#pragma unroll
            for (int i = 0; i < 4; i++) sacc[nt][i] = 0.f;

#pragma unroll
        for (int kt = 0; kt < 4; kt++) {
            const int kk = kt * 16;
#pragma unroll
            for (int nt = 0; nt < 8; nt++) {
                uint32_t b0 = *(const uint32_t*)&Kb[(nt * 8 + r) * AT_STH + kk + 2*c    ];
                uint32_t b1 = *(const uint32_t*)&Kb[(nt * 8 + r) * AT_STH + kk + 2*c + 8];
                MMA_F16(sacc[nt], qf[kt], b0, b1);
            }
        }

        float mx0 = -1e30f, mx1 = -1e30f;
#pragma unroll
        for (int nt = 0; nt < 8; nt++) {
            mx0 = fmaxf(mx0, fmaxf(sacc[nt][0], sacc[nt][1]));
            mx1 = fmaxf(mx1, fmaxf(sacc[nt][2], sacc[nt][3]));
        }
        mx0 = fmaxf(mx0, __shfl_xor_sync(0xffffffffu, mx0, 1));
        mx0 = fmaxf(mx0, __shfl_xor_sync(0xffffffffu, mx0, 2));
        mx1 = fmaxf(mx1, __shfl_xor_sync(0xffffffffu, mx1, 1));
        mx1 = fmaxf(mx1, __shfl_xor_sync(0xffffffffu, mx1, 2));

        float mn0 = fmaxf(m0, mx0 * scale);
        float mn1 = fmaxf(m1, mx1 * scale);
        float a0 = __expf(m0 - mn0), a1 = __expf(m1 - mn1);
        m0 = mn0; m1 = mn1;

        uint32_t ph[8][2];
        float rs0 = 0.f, rs1 = 0.f;
#pragma unroll
        for (int nt = 0; nt < 8; nt++) {
            float p00 = __expf(sacc[nt][0] * scale - mn0);
            float p01 = __expf(sacc[nt][1] * scale - mn0);
            float p10 = __expf(sacc[nt][2] * scale - mn1);
            float p11 = __expf(sacc[nt][3] * scale - mn1);
            rs0 += p00 + p01; rs1 += p10 + p11;
            ph[nt][0] = packh2(p00, p01);
            ph[nt][1] = packh2(p10, p11);
        }
        rs0 += __shfl_xor_sync(0xffffffffu, rs0, 1);
        rs0 += __shfl_xor_sync(0xffffffffu, rs0, 2);
        rs1 += __shfl_xor_sync(0xffffffffu, rs1, 1);
        rs1 += __shfl_xor_sync(0xffffffffu, rs1, 2);
        l0 = l0 * a0 + rs0;
        l1 = l1 * a1 + rs1;
#pragma unroll
        for (int nt = 0; nt < 8; nt++) {
            oacc[nt][0] *= a0; oacc[nt][1] *= a0;
            oacc[nt][2] *= a1; oacc[nt][3] *= a1;
        }

#pragma unroll
        for (int kt = 0; kt < 4; kt++) {
            uint32_t af[4];
            af[0] = ph[2*kt    ][0];
            af[1] = ph[2*kt    ][1];
            af[2] = ph[2*kt + 1][0];
            af[3] = ph[2*kt + 1][1];
#pragma unroll
            for (int ntp = 0; ntp < 4; ntp++) {
                uint32_t v0, v1, v2, v3;
                uint32_t addr = (uint32_t)__cvta_generic_to_shared(
                    &Vb[(kt * 16 + lm_row) * AT_STH + ntp * 16 + lm_col]);
                LDSM_X4_TRANS(v0, v1, v2, v3, addr);
                MMA_F16(oacc[2*ntp    ], af, v0, v1);
                MMA_F16(oacc[2*ntp + 1], af, v2, v3);
            }
        }
        __syncthreads();
    }

    const float inv0 = 1.f / l0, inv1 = 1.f / l1;
    const int row0 = q0 + w * 16 + r;
#pragma unroll
    for (int nt = 0; nt < 8; nt++) {
        const int col = nt * 8 + 2 * c;
        *(__half2*)&O16[base + (size_t)row0 * D_MODEL + col] =
            __floats2half2_rn(oacc[nt][0] * inv0, oacc[nt][1] * inv0);
        *(__half2*)&O16[base + (size_t)(row0 + 8) * D_MODEL + col] =
            __floats2half2_rn(oacc[nt][2] * inv1, oacc[nt][3] * inv1);
    }
}

/* ------------------------------------------------------------------ */
/* Fused residual add + LayerNorm; optional fp16 mirror output         */
/* ------------------------------------------------------------------ */
__global__ __launch_bounds__(256)
void add_ln_kernel(const float* __restrict__ A,
                   const float* __restrict__ B,
                   const float* __restrict__ gamma,
                   const float* __restrict__ beta,
                   float* __restrict__ out,
                   __half* __restrict__ out16)
{
    const int row = blockIdx.x;
    const int t = threadIdx.x;
    const size_t roff = (size_t)row * D_MODEL;

    float4 va = *(const float4*)&A[roff + t * 4];
    float4 vb = *(const float4*)&B[roff + t * 4];
    float v0 = va.x + vb.x, v1 = va.y + vb.y, v2 = va.z + vb.z, v3 = va.w + vb.w;

    float s  = v0 + v1 + v2 + v3;
    float s2 = v0 * v0 + v1 * v1 + v2 * v2 + v3 * v3;

    __shared__ float red[2][8];
#pragma unroll
    for (int off = 16; off > 0; off >>= 1) {
        s  += __shfl_xor_sync(0xffffffffu, s,  off);
        s2 += __shfl_xor_sync(0xffffffffu, s2, off);
    }
    int warp = t >> 5, lane = t & 31;
    if (lane == 0) { red[0][warp] = s; red[1][warp] = s2; }
    __syncthreads();
    if (warp == 0) {
        s  = red[0][lane & 7];
        s2 = red[1][lane & 7];
#pragma unroll
        for (int off = 4; off > 0; off >>= 1) {
            s  += __shfl_xor_sync(0xffffffffu, s,  off);
            s2 += __shfl_xor_sync(0xffffffffu, s2, off);
        }
        if (lane == 0) { red[0][0] = s; red[1][0] = s2; }
    }
    __syncthreads();
    s  = red[0][0];
    s2 = red[1][0];

    const float inv_n = 1.f / (float)D_MODEL;
    float mu   = s * inv_n;
    float var  = s2 * inv_n - mu * mu;
    float rstd = rsqrtf(var + LN_EPS);

    float4 g4  = *(const float4*)&gamma[t * 4];
    float4 be4 = *(const float4*)&beta[t * 4];
    float4 o;
    o.x = (v0 - mu) * rstd * g4.x + be4.x;
    o.y = (v1 - mu) * rstd * g4.y + be4.y;
    o.z = (v2 - mu) * rstd * g4.z + be4.z;
    o.w = (v3 - mu) * rstd * g4.w + be4.w;
    *(float4*)&out[roff + t * 4] = o;
    if (out16) {
        *(__half2*)&out16[roff + t * 4]     = __floats2half2_rn(o.x, o.y);
        *(__half2*)&out16[roff + t * 4 + 2] = __floats2half2_rn(o.z, o.w);
    }
}

/* ------------------------------------------------------------------ */
/* Launcher                                                            */
/* ------------------------------------------------------------------ */
extern "C" void kernel_launch(void* const* d_in, const int* in_sizes, int n_in,
                              void* d_out, int out_size)
{
    const float* x   = (const float*)d_in[0];
    const float* Wq  = (const float*)d_in[1];
    const float* bq  = (const float*)d_in[2];
    const float* Wk  = (const float*)d_in[3];
    const float* bk  = (const float*)d_in[4];
    const float* Wv  = (const float*)d_in[5];
    const float* bv  = (const float*)d_in[6];
    const float* Wo  = (const float*)d_in[7];
    const float* bo  = (const float*)d_in[8];
    const float* W1  = (const float*)d_in[9];
    const float* b1  = (const float*)d_in[10];
    const float* W2  = (const float*)d_in[11];
    const float* b2  = (const float*)d_in[12];
    const float* g1  = (const float*)d_in[13];
    const float* be1 = (const float*)d_in[14];
    const float* g2  = (const float*)d_in[15];
    const float* be2 = (const float*)d_in[16];
    float* out = (float*)d_out;

    float *proj, *h, *f2;
    cudaGetSymbolAddress((void**)&proj, g_proj);
    cudaGetSymbolAddress((void**)&h,    g_h);
    cudaGetSymbolAddress((void**)&f2,   g_f2);

    __half *x16, *wq16, *wk16, *wv16, *wo16, *w116, *w216;
    __half *q16, *k16, *v16, *att16, *h16, *ffn16;
    cudaGetSymbolAddress((void**)&x16,   g_x16);
    cudaGetSymbolAddress((void**)&wq16,  g_wq16);
    cudaGetSymbolAddress((void**)&wk16,  g_wk16);
    cudaGetSymbolAddress((void**)&wv16,  g_wv16);
    cudaGetSymbolAddress((void**)&wo16,  g_wo16);
    cudaGetSymbolAddress((void**)&w116,  g_w116);
    cudaGetSymbolAddress((void**)&w216,  g_w216);
    cudaGetSymbolAddress((void**)&q16,   g_q16);
    cudaGetSymbolAddress((void**)&k16,   g_k16);
    cudaGetSymbolAddress((void**)&v16,   g_v16);
    cudaGetSymbolAddress((void**)&att16, g_att16);
    cudaGetSymbolAddress((void**)&h16,   g_h16);
    cudaGetSymbolAddress((void**)&ffn16, g_ffn16);

    static int attr_set = 0;
    if (!attr_set) {
        cudaFuncSetAttribute(attn_h_kernel,
                             cudaFuncAttributeMaxDynamicSharedMemorySize, AT_SMEM_B);
        cudaFuncSetAttribute(gemm_h<false, false>,
                             cudaFuncAttributeMaxDynamicSharedMemorySize, GEMM_SMEM_B);
        cudaFuncSetAttribute(gemm_h<true, true>,
                             cudaFuncAttributeMaxDynamicSharedMemorySize, GEMM_SMEM_B);
        cudaFuncSetAttribute(gemm_h_qkv,
                             cudaFuncAttributeMaxDynamicSharedMemorySize, GEMM_SMEM_B);
        attr_set = 1;
    }

    dim3 blk(256);

    /* fused fp32->fp16 conversion (x + all 6 weights, one launch) */
    ConvAll ca;
    ca.s[0] = x;   ca.d[0] = x16;
    ca.s[1] = Wq;  ca.d[1] = wq16;
    ca.s[2] = Wk;  ca.d[2] = wk16;
    ca.s[3] = Wv;  ca.d[3] = wv16;
    ca.s[4] = Wo;  ca.d[4] = wo16;
    ca.s[5] = W1;  ca.d[5] = w116;
    ca.s[6] = W2;  ca.d[6] = w216;
    /* total = 16M elems, 2048 per CTA */
    f2h_all_kernel<<<(16u << 20) / 2048, blk>>>(ca);

    /* merged QKV projections -> fp16 q,k,v */
    TriParams tp;
    tp.W[0] = wq16; tp.W[1] = wk16; tp.W[2] = wv16;
    tp.b[0] = bq;   tp.b[1] = bk;   tp.b[2] = bv;
    tp.C[0] = q16;  tp.C[1] = k16;  tp.C[2] = v16;
    dim3 g_qkv(D_MODEL / 128, NTOK / 128, 3);
    gemm_h_qkv<<<g_qkv, blk, GEMM_SMEM_B>>>(x16, tp, D_MODEL, D_MODEL);

    /* fp16 flash attention -> att16 */
    dim3 g_at(SEQ / 128, NHEAD, BATCH);
    attn_h_kernel<<<g_at, blk, AT_SMEM_B>>>(q16, k16, v16, att16);

    /* output projection (fp16 in, fp32 out) */
    dim3 g_sq(D_MODEL / 128, NTOK / 128);
    gemm_h<false, false><<<g_sq, blk, GEMM_SMEM_B>>>(att16, wo16, bo, proj,
                                                     (__half*)0, D_MODEL, D_MODEL);

    /* h = LN(x + proj), also h16 */
    add_ln_kernel<<<NTOK, blk>>>(x, proj, g1, be1, h, h16);

    /* FFN1 (ReLU, fp16 out) */
    dim3 g_f1(D_FF / 128, NTOK / 128);
    gemm_h<true, true><<<g_f1, blk, GEMM_SMEM_B>>>(h16, w116, b1, (float*)0,
                                                   ffn16, D_FF, D_MODEL);
    /* FFN2 (fp32 out) */
    gemm_h<false, false><<<g_sq, blk, GEMM_SMEM_B>>>(ffn16, w216, b2, f2,
                                                     (__half*)0, D_MODEL, D_FF);

    /* out = LN(h + f2) */
    add_ln_kernel<<<NTOK, blk>>>(h, f2, g2, be2, out, (__half*)0);
}

// round 17
// speedup vs baseline: 1.1113x; 1.1113x over previous
#include <cuda_runtime.h>
#include <cuda_fp16.h>
#include <cstdint>

#define D_MODEL 1024
#define NHEAD 16
#define D_HEAD 64
#define D_FF 4096
#define BATCH 2
#define SEQ 2048
#define NTOK (BATCH*SEQ)   /* 4096 tokens */
#define LN_EPS 1e-5f

/* ------------------------------------------------------------------ */
/* Scratch (static __device__ arrays; no runtime allocation)           */
/* ------------------------------------------------------------------ */
__device__ float  g_proj[(size_t)NTOK * D_MODEL];
__device__ float  g_h   [(size_t)NTOK * D_MODEL];
__device__ float  g_f2  [(size_t)NTOK * D_MODEL];

__device__ __half g_x16  [(size_t)NTOK * D_MODEL];
__device__ __half g_wq16 [(size_t)D_MODEL * D_MODEL];
__device__ __half g_wk16 [(size_t)D_MODEL * D_MODEL];
__device__ __half g_wv16 [(size_t)D_MODEL * D_MODEL];
__device__ __half g_wo16 [(size_t)D_MODEL * D_MODEL];
__device__ __half g_w116 [(size_t)D_FF * D_MODEL];
__device__ __half g_w216 [(size_t)D_MODEL * D_FF];
__device__ __half g_q16  [(size_t)NTOK * D_MODEL];
__device__ __half g_k16  [(size_t)NTOK * D_MODEL];
__device__ __half g_v16  [(size_t)NTOK * D_MODEL];
__device__ __half g_att16[(size_t)NTOK * D_MODEL];
__device__ __half g_h16  [(size_t)NTOK * D_MODEL];
__device__ __half g_ffn16[(size_t)NTOK * D_FF];

/* fp16 MMA, fp32 accumulate */
#define MMA_F16(acc, a, b0, b1)                                         \
    asm volatile(                                                       \
        "mma.sync.aligned.m16n8k16.row.col.f32.f16.f16.f32 "            \
        "{%0,%1,%2,%3}, {%4,%5,%6,%7}, {%8,%9}, {%0,%1,%2,%3};\n"       \
        : "+f"(acc[0]), "+f"(acc[1]), "+f"(acc[2]), "+f"(acc[3])        \
        : "r"(a[0]), "r"(a[1]), "r"(a[2]), "r"(a[3]), "r"(b0), "r"(b1))

#define LDSM_X4(d0, d1, d2, d3, addr)                                   \
    asm volatile(                                                       \
        "ldmatrix.sync.aligned.m8n8.x4.shared.b16 "                     \
        "{%0,%1,%2,%3}, [%4];"                                          \
        : "=r"(d0), "=r"(d1), "=r"(d2), "=r"(d3) : "r"(addr))

#define LDSM_X4_TRANS(d0, d1, d2, d3, addr)                             \
    asm volatile(                                                       \
        "ldmatrix.sync.aligned.m8n8.x4.trans.shared.b16 "               \
        "{%0,%1,%2,%3}, [%4];"                                          \
        : "=r"(d0), "=r"(d1), "=r"(d2), "=r"(d3) : "r"(addr))

__device__ __forceinline__ void cpa16(void* s, const void* g) {
    uint32_t sa = (uint32_t)__cvta_generic_to_shared(s);
    asm volatile("cp.async.cg.shared.global [%0], [%1], 16;" :: "r"(sa), "l"(g));
}
#define CP_COMMIT() asm volatile("cp.async.commit_group;")
#define CP_WAIT0()  asm volatile("cp.async.wait_group 0;")
#define CP_WAIT1()  asm volatile("cp.async.wait_group 1;")

__device__ __forceinline__ uint32_t packh2(float a, float b) {
    __half2 h = __floats2half2_rn(a, b);
    return *(uint32_t*)&h;
}
__device__ __forceinline__ uint32_t smaddr(const void* p) {
    return (uint32_t)__cvta_generic_to_shared(p);
}

/* ------------------------------------------------------------------ */
/* fused fp32 -> fp16 convert: all 7 tensors in ONE launch.            */
/* ------------------------------------------------------------------ */
struct ConvAll {
    const float* s[7];
    __half*      d[7];
};

__global__ __launch_bounds__(256)
void f2h_all_kernel(ConvAll p)
{
    const size_t M1 = 1u << 20;
    size_t i = ((size_t)blockIdx.x * 256 + threadIdx.x) * 8;

    int seg; size_t off;
    if      (i <  4*M1) { seg = 0; off = 0;     }
    else if (i <  5*M1) { seg = 1; off = 4*M1;  }
    else if (i <  6*M1) { seg = 2; off = 5*M1;  }
    else if (i <  7*M1) { seg = 3; off = 6*M1;  }
    else if (i <  8*M1) { seg = 4; off = 7*M1;  }
    else if (i < 12*M1) { seg = 5; off = 8*M1;  }
    else                { seg = 6; off = 12*M1; }

    const float* s = p.s[seg];
    __half*      d = p.d[seg];
    const size_t j = i - off;

    float4 a = *(const float4*)&s[j];
    float4 b = *(const float4*)&s[j + 4];
    __half2 h0 = __floats2half2_rn(a.x, a.y);
    __half2 h1 = __floats2half2_rn(a.z, a.w);
    __half2 h2 = __floats2half2_rn(b.x, b.y);
    __half2 h3 = __floats2half2_rn(b.z, b.w);
    uint4 o;
    o.x = *(uint32_t*)&h0; o.y = *(uint32_t*)&h1;
    o.z = *(uint32_t*)&h2; o.w = *(uint32_t*)&h3;
    *(uint4*)&d[j] = o;
}

/* ------------------------------------------------------------------ */
/* fp16 GEMM:  C[M,N] = A[M,K] @ B[N,K]^T + bias (opt ReLU, opt fp16)  */
/* BM=BN=128, BK=32, 256 thr, warp tile 64x32, m16n8k16               */
/* 3-stage cp.async ring; fragment loads via ldmatrix.x4.              */
/* ------------------------------------------------------------------ */
#define GST 40
#define GTILE_H (128 * GST)
#define GSTAGES 3
#define GEMM_SMEM_B (GSTAGES * 2 * GTILE_H * (int)sizeof(__half))

template<bool RELU, bool HOUT>
__device__ __forceinline__
void gemm_h_body(const __half* __restrict__ A,
                 const __half* __restrict__ B,
                 const float* __restrict__ bias,
                 float* __restrict__ C,
                 __half* __restrict__ C16,
                 int N, int K, __half* smem)
{
    const int bm0 = blockIdx.y * 128;
    const int bn0 = blockIdx.x * 128;
    const int t    = threadIdx.x;
    const int warp = t >> 5, lane = t & 31;
    const int wm = (warp >> 2) * 64;
    const int wn = (warp & 3) * 32;
    const int r  = lane >> 2;
    const int c  = lane & 3;

    __half* As = smem;
    __half* Bs = smem + GSTAGES * GTILE_H;

    /* ldmatrix lane addressing (within a k-chunk base):
       A (.x4, 16x16 tile):  row = m0 + (lane&15),           col = kk + (lane>>4)*8
       B (.x4, two 8x16):    row = n0 + (lane>>4)*8+(lane&7), col = kk + ((lane>>3)&1)*8 */
    const int a_row = lane & 15;
    const int a_col = (lane >> 4) * 8;
    const int b_row = ((lane >> 4) * 8) | (lane & 7);
    const int b_col = ((lane >> 3) & 1) * 8;

    float acc[4][4][4];
#pragma unroll
    for (int mt = 0; mt < 4; mt++)
#pragma unroll
        for (int nt = 0; nt < 4; nt++)
#pragma unroll
            for (int i = 0; i < 4; i++) acc[mt][nt][i] = 0.f;

    int g_row[2], g_sg[2];
#pragma unroll
    for (int i = 0; i < 2; i++) {
        int slot = t + i * 256;
        g_row[i] = slot >> 2;
        g_sg[i]  = slot & 3;
    }

    const int niter = K >> 5;

#pragma unroll
    for (int s = 0; s < GSTAGES - 1; ++s) {
        const int k0 = s << 5;
#pragma unroll
        for (int i = 0; i < 2; i++) {
            cpa16(&As[s * GTILE_H + g_row[i] * GST + g_sg[i] * 8],
                  A + (size_t)(bm0 + g_row[i]) * K + k0 + g_sg[i] * 8);
            cpa16(&Bs[s * GTILE_H + g_row[i] * GST + g_sg[i] * 8],
                  B + (size_t)(bn0 + g_row[i]) * K + k0 + g_sg[i] * 8);
        }
        CP_COMMIT();
    }

    int buf = 0;
    for (int it = 0; it < niter; ++it) {
        CP_WAIT1();
        __syncthreads();

        const __half* Ab = As + buf * GTILE_H;
        const __half* Bb = Bs + buf * GTILE_H;
#pragma unroll
        for (int ks = 0; ks < 2; ++ks) {
            const int kk = ks * 16;
            uint32_t af[4][4], bf[4][2];
#pragma unroll
            for (int mt = 0; mt < 4; mt++) {
                uint32_t ad = smaddr(&Ab[(wm + mt * 16 + a_row) * GST + kk + a_col]);
                LDSM_X4(af[mt][0], af[mt][1], af[mt][2], af[mt][3], ad);
            }
#pragma unroll
            for (int p = 0; p < 2; p++) {
                uint32_t bd = smaddr(&Bb[(wn + p * 16 + b_row) * GST + kk + b_col]);
                LDSM_X4(bf[2*p][0], bf[2*p][1], bf[2*p+1][0], bf[2*p+1][1], bd);
            }
#pragma unroll
            for (int mt = 0; mt < 4; mt++)
#pragma unroll
                for (int nt = 0; nt < 4; nt++)
                    MMA_F16(acc[mt][nt], af[mt], bf[nt][0], bf[nt][1]);
        }

        const int nt_tile = it + GSTAGES - 1;
        if (nt_tile < niter) {
            const int ns = nt_tile % GSTAGES;
            const int k0 = nt_tile << 5;
#pragma unroll
            for (int i = 0; i < 2; i++) {
                cpa16(&As[ns * GTILE_H + g_row[i] * GST + g_sg[i] * 8],
                      A + (size_t)(bm0 + g_row[i]) * K + k0 + g_sg[i] * 8);
                cpa16(&Bs[ns * GTILE_H + g_row[i] * GST + g_sg[i] * 8],
                      B + (size_t)(bn0 + g_row[i]) * K + k0 + g_sg[i] * 8);
            }
            CP_COMMIT();
        }
        buf = (buf + 1 == GSTAGES) ? 0 : buf + 1;
    }

#pragma unroll
    for (int mt = 0; mt < 4; mt++) {
        const int mrow = bm0 + wm + mt * 16 + r;
#pragma unroll
        for (int nt = 0; nt < 4; nt++) {
            const int col = bn0 + wn + nt * 8 + 2 * c;
            const float b0 = bias[col], b1 = bias[col + 1];
            float o0 = acc[mt][nt][0] + b0;
            float o1 = acc[mt][nt][1] + b1;
            float o2 = acc[mt][nt][2] + b0;
            float o3 = acc[mt][nt][3] + b1;
            if (RELU) {
                o0 = fmaxf(o0, 0.f); o1 = fmaxf(o1, 0.f);
                o2 = fmaxf(o2, 0.f); o3 = fmaxf(o3, 0.f);
            }
            if (HOUT) {
                *(__half2*)&C16[(size_t)mrow * N + col]       = __floats2half2_rn(o0, o1);
                *(__half2*)&C16[(size_t)(mrow + 8) * N + col] = __floats2half2_rn(o2, o3);
            } else {
                *(float2*)&C[(size_t)mrow * N + col]       = make_float2(o0, o1);
                *(float2*)&C[(size_t)(mrow + 8) * N + col] = make_float2(o2, o3);
            }
        }
    }
}

template<bool RELU, bool HOUT>
__global__ __launch_bounds__(256, 2)
void gemm_h(const __half* __restrict__ A, const __half* __restrict__ B,
            const float* __restrict__ bias, float* __restrict__ C,
            __half* __restrict__ C16, int N, int K)
{
    extern __shared__ __half hsm[];
    gemm_h_body<RELU, HOUT>(A, B, bias, C, C16, N, K, hsm);
}

struct TriParams {
    const __half* W[3];
    const float*  b[3];
    __half*       C[3];
};

__global__ __launch_bounds__(256, 2)
void gemm_h_qkv(const __half* __restrict__ A, TriParams p, int N, int K)
{
    extern __shared__ __half hsm[];
    const int z = blockIdx.z;
    gemm_h_body<false, true>(A, p.W[z], p.b[z], (float*)0, p.C[z], N, K, hsm);
}

/* ------------------------------------------------------------------ */
/* fp16 tensor-core flash attention; K fragments via ldmatrix.x4.      */
/* ------------------------------------------------------------------ */
#define AT_STH 72
#define AT_Q_H   (128 * AT_STH)
#define AT_KV_H  (64 * AT_STH)
#define AT_SMEM_B ((AT_Q_H + 4 * AT_KV_H) * (int)sizeof(__half))

__global__ __launch_bounds__(256)
void attn_h_kernel(const __half* __restrict__ Q,
                   const __half* __restrict__ K,
                   const __half* __restrict__ V,
                   __half* __restrict__ O16)
{
    extern __shared__ __half asm_h[];
    __half* Qs = asm_h;
    __half* Ks = asm_h + AT_Q_H;
    __half* Vs = asm_h + AT_Q_H + 2 * AT_KV_H;

    const int b  = blockIdx.z, h = blockIdx.y;
    const int q0 = blockIdx.x * 128;
    const int t = threadIdx.x, w = t >> 5, lane = t & 31;
    const int r = lane >> 2, c = lane & 3;
    const size_t base = ((size_t)b * SEQ) * D_MODEL + (size_t)h * D_HEAD;

#pragma unroll
    for (int i = 0; i < 2; i++) {
        int slot = t + i * 256;
        int row = slot >> 3, sg = slot & 7;
        cpa16(&Ks[row * AT_STH + sg * 8], K + base + (size_t)row * D_MODEL + sg * 8);
        cpa16(&Vs[row * AT_STH + sg * 8], V + base + (size_t)row * D_MODEL + sg * 8);
    }
    CP_COMMIT();

#pragma unroll
    for (int i = 0; i < 4; i++) {
        int slot = t + i * 256;
        int row = slot >> 3, sg = slot & 7;
        cpa16(&Qs[row * AT_STH + sg * 8],
              Q + base + (size_t)(q0 + row) * D_MODEL + sg * 8);
    }
    CP_COMMIT();
    CP_WAIT0();
    __syncthreads();

    uint32_t qf[4][4];
#pragma unroll
    for (int kt = 0; kt < 4; kt++) {
        const int kk = kt * 16;
        qf[kt][0] = *(const uint32_t*)&Qs[(w * 16 + r    ) * AT_STH + kk + 2*c    ];
        qf[kt][1] = *(const uint32_t*)&Qs[(w * 16 + r + 8) * AT_STH + kk + 2*c    ];
        qf[kt][2] = *(const uint32_t*)&Qs[(w * 16 + r    ) * AT_STH + kk + 2*c + 8];
        qf[kt][3] = *(const uint32_t*)&Qs[(w * 16 + r + 8) * AT_STH + kk + 2*c + 8];
    }

    float oacc[8][4];
#pragma unroll
    for (int nt = 0; nt < 8; nt++)
#pragma unroll
        for (int i = 0; i < 4; i++) oacc[nt][i] = 0.f;
    float m0 = -1e30f, m1 = -1e30f, l0 = 0.f, l1 = 0.f;
    const float scale = 0.125f;

    const int lm_row = lane & 15;
    const int lm_col = (lane >> 4) * 8;
    /* K ldmatrix (non-trans, two 8x16 row-tiles per .x4) */
    const int kb_row = ((lane >> 4) * 8) | (lane & 7);
    const int kb_col = ((lane >> 3) & 1) * 8;

    const int ntiles = SEQ / 64;
    for (int it = 0; it < ntiles; ++it) {
        const int buf = it & 1;
        const bool has_next = (it + 1 < ntiles);
        __half* Kb = Ks + buf * AT_KV_H;
        __half* Vb = Vs + buf * AT_KV_H;

        if (has_next) {
            const int k0n = (it + 1) * 64;
            const int nb = buf ^ 1;
#pragma unroll
            for (int i = 0; i < 2; i++) {
                int slot = t + i * 256;
                int row = slot >> 3, sg = slot & 7;
                cpa16(&Ks[nb * AT_KV_H + row * AT_STH + sg * 8],
                      K + base + (size_t)(k0n + row) * D_MODEL + sg * 8);
                cpa16(&Vs[nb * AT_KV_H + row * AT_STH + sg * 8],
                      V + base + (size_t)(k0n + row) * D_MODEL + sg * 8);
            }
            CP_COMMIT();
            CP_WAIT1();
        } else {
            CP_WAIT0();
        }
        __syncthreads();

        float sacc[8][4];
#pragma unroll
        for (int nt = 0; nt < 8; nt++)
#pragma unroll
            for (int i = 0; i < 4; i++) sacc[nt][i] = 0.f;

#pragma unroll
        for (int kt = 0; kt < 4; kt++) {
            const int kk = kt * 16;
#pragma unroll
            for (int p = 0; p < 4; p++) {
                uint32_t b0, b1, b2, b3;
                uint32_t kd = smaddr(&Kb[(p * 16 + kb_row) * AT_STH + kk + kb_col]);
                LDSM_X4(b0, b1, b2, b3, kd);
                MMA_F16(sacc[2*p    ], qf[kt], b0, b1);
                MMA_F16(sacc[2*p + 1], qf[kt], b2, b3);
            }
        }

        float mx0 = -1e30f, mx1 = -1e30f;
#pragma unroll
        for (int nt = 0; nt < 8; nt++) {
            mx0 = fmaxf(mx0, fmaxf(sacc[nt][0], sacc[nt][1]));
            mx1 = fmaxf(mx1, fmaxf(sacc[nt][2], sacc[nt][3]));
        }
        mx0 = fmaxf(mx0, __shfl_xor_sync(0xffffffffu, mx0, 1));
        mx0 = fmaxf(mx0, __shfl_xor_sync(0xffffffffu, mx0, 2));
        mx1 = fmaxf(mx1, __shfl_xor_sync(0xffffffffu, mx1, 1));
        mx1 = fmaxf(mx1, __shfl_xor_sync(0xffffffffu, mx1, 2));

        float mn0 = fmaxf(m0, mx0 * scale);
        float mn1 = fmaxf(m1, mx1 * scale);
        float a0 = __expf(m0 - mn0), a1 = __expf(m1 - mn1);
        m0 = mn0; m1 = mn1;

        uint32_t ph[8][2];
        float rs0 = 0.f, rs1 = 0.f;
#pragma unroll
        for (int nt = 0; nt < 8; nt++) {
            float p00 = __expf(sacc[nt][0] * scale - mn0);
            float p01 = __expf(sacc[nt][1] * scale - mn0);
            float p10 = __expf(sacc[nt][2] * scale - mn1);
            float p11 = __expf(sacc[nt][3] * scale - mn1);
            rs0 += p00 + p01; rs1 += p10 + p11;
            ph[nt][0] = packh2(p00, p01);
            ph[nt][1] = packh2(p10, p11);
        }
        rs0 += __shfl_xor_sync(0xffffffffu, rs0, 1);
        rs0 += __shfl_xor_sync(0xffffffffu, rs0, 2);
        rs1 += __shfl_xor_sync(0xffffffffu, rs1, 1);
        rs1 += __shfl_xor_sync(0xffffffffu, rs1, 2);
        l0 = l0 * a0 + rs0;
        l1 = l1 * a1 + rs1;
#pragma unroll
        for (int nt = 0; nt < 8; nt++) {
            oacc[nt][0] *= a0; oacc[nt][1] *= a0;
            oacc[nt][2] *= a1; oacc[nt][3] *= a1;
        }

#pragma unroll
        for (int kt = 0; kt < 4; kt++) {
            uint32_t af[4];
            af[0] = ph[2*kt    ][0];
            af[1] = ph[2*kt    ][1];
            af[2] = ph[2*kt + 1][0];
            af[3] = ph[2*kt + 1][1];
#pragma unroll
            for (int ntp = 0; ntp < 4; ntp++) {
                uint32_t v0, v1, v2, v3;
                uint32_t addr = smaddr(
                    &Vb[(kt * 16 + lm_row) * AT_STH + ntp * 16 + lm_col]);
                LDSM_X4_TRANS(v0, v1, v2, v3, addr);
                MMA_F16(oacc[2*ntp    ], af, v0, v1);
                MMA_F16(oacc[2*ntp + 1], af, v2, v3);
            }
        }
        __syncthreads();
    }

    const float inv0 = 1.f / l0, inv1 = 1.f / l1;
    const int row0 = q0 + w * 16 + r;
#pragma unroll
    for (int nt = 0; nt < 8; nt++) {
        const int col = nt * 8 + 2 * c;
        *(__half2*)&O16[base + (size_t)row0 * D_MODEL + col] =
            __floats2half2_rn(oacc[nt][0] * inv0, oacc[nt][1] * inv0);
        *(__half2*)&O16[base + (size_t)(row0 + 8) * D_MODEL + col] =
            __floats2half2_rn(oacc[nt][2] * inv1, oacc[nt][3] * inv1);
    }
}

/* ------------------------------------------------------------------ */
/* Fused residual add + LayerNorm; optional fp16 mirror output         */
/* ------------------------------------------------------------------ */
__global__ __launch_bounds__(256)
void add_ln_kernel(const float* __restrict__ A,
                   const float* __restrict__ B,
                   const float* __restrict__ gamma,
                   const float* __restrict__ beta,
                   float* __restrict__ out,
                   __half* __restrict__ out16)
{
    const int row = blockIdx.x;
    const int t = threadIdx.x;
    const size_t roff = (size_t)row * D_MODEL;

    float4 va = *(const float4*)&A[roff + t * 4];
    float4 vb = *(const float4*)&B[roff + t * 4];
    float v0 = va.x + vb.x, v1 = va.y + vb.y, v2 = va.z + vb.z, v3 = va.w + vb.w;

    float s  = v0 + v1 + v2 + v3;
    float s2 = v0 * v0 + v1 * v1 + v2 * v2 + v3 * v3;

    __shared__ float red[2][8];
#pragma unroll
    for (int off = 16; off > 0; off >>= 1) {
        s  += __shfl_xor_sync(0xffffffffu, s,  off);
        s2 += __shfl_xor_sync(0xffffffffu, s2, off);
    }
    int warp = t >> 5, lane = t & 31;
    if (lane == 0) { red[0][warp] = s; red[1][warp] = s2; }
    __syncthreads();
    if (warp == 0) {
        s  = red[0][lane & 7];
        s2 = red[1][lane & 7];
#pragma unroll
        for (int off = 4; off > 0; off >>= 1) {
            s  += __shfl_xor_sync(0xffffffffu, s,  off);
            s2 += __shfl_xor_sync(0xffffffffu, s2, off);
        }
        if (lane == 0) { red[0][0] = s; red[1][0] = s2; }
    }
    __syncthreads();
    s  = red[0][0];
    s2 = red[1][0];

    const float inv_n = 1.f / (float)D_MODEL;
    float mu   = s * inv_n;
    float var  = s2 * inv_n - mu * mu;
    float rstd = rsqrtf(var + LN_EPS);

    float4 g4  = *(const float4*)&gamma[t * 4];
    float4 be4 = *(const float4*)&beta[t * 4];
    float4 o;
    o.x = (v0 - mu) * rstd * g4.x + be4.x;
    o.y = (v1 - mu) * rstd * g4.y + be4.y;
    o.z = (v2 - mu) * rstd * g4.z + be4.z;
    o.w = (v3 - mu) * rstd * g4.w + be4.w;
    *(float4*)&out[roff + t * 4] = o;
    if (out16) {
        *(__half2*)&out16[roff + t * 4]     = __floats2half2_rn(o.x, o.y);
        *(__half2*)&out16[roff + t * 4 + 2] = __floats2half2_rn(o.z, o.w);
    }
}

/* ------------------------------------------------------------------ */
/* Launcher                                                            */
/* ------------------------------------------------------------------ */
extern "C" void kernel_launch(void* const* d_in, const int* in_sizes, int n_in,
                              void* d_out, int out_size)
{
    const float* x   = (const float*)d_in[0];
    const float* Wq  = (const float*)d_in[1];
    const float* bq  = (const float*)d_in[2];
    const float* Wk  = (const float*)d_in[3];
    const float* bk  = (const float*)d_in[4];
    const float* Wv  = (const float*)d_in[5];
    const float* bv  = (const float*)d_in[6];
    const float* Wo  = (const float*)d_in[7];
    const float* bo  = (const float*)d_in[8];
    const float* W1  = (const float*)d_in[9];
    const float* b1  = (const float*)d_in[10];
    const float* W2  = (const float*)d_in[11];
    const float* b2  = (const float*)d_in[12];
    const float* g1  = (const float*)d_in[13];
    const float* be1 = (const float*)d_in[14];
    const float* g2  = (const float*)d_in[15];
    const float* be2 = (const float*)d_in[16];
    float* out = (float*)d_out;

    float *proj, *h, *f2;
    cudaGetSymbolAddress((void**)&proj, g_proj);
    cudaGetSymbolAddress((void**)&h,    g_h);
    cudaGetSymbolAddress((void**)&f2,   g_f2);

    __half *x16, *wq16, *wk16, *wv16, *wo16, *w116, *w216;
    __half *q16, *k16, *v16, *att16, *h16, *ffn16;
    cudaGetSymbolAddress((void**)&x16,   g_x16);
    cudaGetSymbolAddress((void**)&wq16,  g_wq16);
    cudaGetSymbolAddress((void**)&wk16,  g_wk16);
    cudaGetSymbolAddress((void**)&wv16,  g_wv16);
    cudaGetSymbolAddress((void**)&wo16,  g_wo16);
    cudaGetSymbolAddress((void**)&w116,  g_w116);
    cudaGetSymbolAddress((void**)&w216,  g_w216);
    cudaGetSymbolAddress((void**)&q16,   g_q16);
    cudaGetSymbolAddress((void**)&k16,   g_k16);
    cudaGetSymbolAddress((void**)&v16,   g_v16);
    cudaGetSymbolAddress((void**)&att16, g_att16);
    cudaGetSymbolAddress((void**)&h16,   g_h16);
    cudaGetSymbolAddress((void**)&ffn16, g_ffn16);

    static int attr_set = 0;
    if (!attr_set) {
        cudaFuncSetAttribute(attn_h_kernel,
                             cudaFuncAttributeMaxDynamicSharedMemorySize, AT_SMEM_B);
        cudaFuncSetAttribute(gemm_h<false, false>,
                             cudaFuncAttributeMaxDynamicSharedMemorySize, GEMM_SMEM_B);
        cudaFuncSetAttribute(gemm_h<true, true>,
                             cudaFuncAttributeMaxDynamicSharedMemorySize, GEMM_SMEM_B);
        cudaFuncSetAttribute(gemm_h_qkv,
                             cudaFuncAttributeMaxDynamicSharedMemorySize, GEMM_SMEM_B);
        attr_set = 1;
    }

    dim3 blk(256);

    /* fused fp32->fp16 conversion (x + all 6 weights, one launch) */
    ConvAll ca;
    ca.s[0] = x;   ca.d[0] = x16;
    ca.s[1] = Wq;  ca.d[1] = wq16;
    ca.s[2] = Wk;  ca.d[2] = wk16;
    ca.s[3] = Wv;  ca.d[3] = wv16;
    ca.s[4] = Wo;  ca.d[4] = wo16;
    ca.s[5] = W1;  ca.d[5] = w116;
    ca.s[6] = W2;  ca.d[6] = w216;
    f2h_all_kernel<<<(16u << 20) / 2048, blk>>>(ca);

    /* merged QKV projections -> fp16 q,k,v */
    TriParams tp;
    tp.W[0] = wq16; tp.W[1] = wk16; tp.W[2] = wv16;
    tp.b[0] = bq;   tp.b[1] = bk;   tp.b[2] = bv;
    tp.C[0] = q16;  tp.C[1] = k16;  tp.C[2] = v16;
    dim3 g_qkv(D_MODEL / 128, NTOK / 128, 3);
    gemm_h_qkv<<<g_qkv, blk, GEMM_SMEM_B>>>(x16, tp, D_MODEL, D_MODEL);

    /* fp16 flash attention -> att16 */
    dim3 g_at(SEQ / 128, NHEAD, BATCH);
    attn_h_kernel<<<g_at, blk, AT_SMEM_B>>>(q16, k16, v16, att16);

    /* output projection (fp16 in, fp32 out) */
    dim3 g_sq(D_MODEL / 128, NTOK / 128);
    gemm_h<false, false><<<g_sq, blk, GEMM_SMEM_B>>>(att16, wo16, bo, proj,
                                                     (__half*)0, D_MODEL, D_MODEL);

    /* h = LN(x + proj), also h16 */
    add_ln_kernel<<<NTOK, blk>>>(x, proj, g1, be1, h, h16);

    /* FFN1 (ReLU, fp16 out) */
    dim3 g_f1(D_FF / 128, NTOK / 128);
    gemm_h<true, true><<<g_f1, blk, GEMM_SMEM_B>>>(h16, w116, b1, (float*)0,
                                                   ffn16, D_FF, D_MODEL);
    /* FFN2 (fp32 out) */
    gemm_h<false, false><<<g_sq, blk, GEMM_SMEM_B>>>(ffn16, w216, b2, f2,
                                                     (__half*)0, D_MODEL, D_FF);

    /* out = LN(h + f2) */
    add_ln_kernel<<<NTOK, blk>>>(h, f2, g2, be2, out, (__half*)0);
}